// round 11
// baseline (speedup 1.0000x reference)
#include <cuda_runtime.h>
#include <cuda_fp16.h>
#include <cstdint>

// ============================================================================
// CINLayer: out_mat[b,c,d] = sum_{i,j} kernel[c,i,j] * x[b,i,d] * y[b,j,d]
//           final[b,c]     = sum_d out_mat[b,c,d]
// GEMM mapping: Z[(b,d),(i,j)] = x[b,i,d]*y[b,j,d] (built in regs, fp16)
//               out = Z(131072 x 1024) @ kernel^T(1024 x 64)
// R11: R8 chassis + f16-ACCUMULATE mma (m16n8k16.f16) with fp32 register
//      flush every 4 k16-steps. Tests the hypothesis that f32-acc mma.sync
//      runs half-rate on sm_103 (all prior rounds ceiling at ~4 cyc/HMMA/SM).
// ============================================================================

#define B_DIM 4096
#define H_DIM 32
#define C_DIM 64
#define D_DIM 32

namespace cin {

constexpr int THREADS   = 256;
constexpr int GRID      = 148;
constexpr int PASS_ROWS = 128;                          // 4 b's x 32 d per pass
constexpr int N_PASSES  = (B_DIM * D_DIM) / PASS_ROWS;  // 1024
constexpr int KSTEPS    = 64;                           // K=1024 / k16

// SMEM (bytes)
constexpr int SM_KP   = 0;                      // packed fp16 kernel: 128KB
constexpr int KP_SZ   = KSTEPS * 4 * 32 * 16;   // 131072
constexpr int XY_STRIDE = 132;                  // stage row stride (words)
constexpr int XS_SZ   = 32 * XY_STRIDE * 4;     // 16896
constexpr int STG_SZ  = 2 * XS_SZ;              // x + y = 33792
constexpr int SM_STG  = SM_KP + KP_SZ;          // two parity buffers
// epilogue buffer aliases the CURRENT (just consumed) stage buffer
constexpr int BUF_STRIDE = 66;                  // even; 128*66*4 = 33792 = STG_SZ
static_assert(PASS_ROWS * BUF_STRIDE * 4 <= STG_SZ, "BUF must fit stage buffer");
constexpr unsigned SMEM_TOTAL = (unsigned)(SM_STG + 2 * STG_SZ);   // 198656

__device__ __forceinline__ uint32_t smem_u32(const void* p) {
    uint32_t a;
    asm("{ .reg .u64 t; cvta.to.shared.u64 t, %1; cvt.u32.u64 %0, t; }"
        : "=r"(a) : "l"(p));
    return a;
}
// pack two f32 -> f16x2 (hi = first arg)
__device__ __forceinline__ uint32_t cvt2(float hi, float lo) {
    uint32_t r;
    asm("cvt.rn.f16x2.f32 %0, %1, %2;" : "=r"(r) : "f"(hi), "f"(lo));
    return r;
}
__device__ __forceinline__ void sts32(uint32_t a, uint32_t v) {
    asm volatile("st.shared.b32 [%0], %1;" :: "r"(a), "r"(v) : "memory");
}
__device__ __forceinline__ void sts64f(uint32_t a, float v0, float v1) {
    asm volatile("st.shared.v2.f32 [%0], {%1,%2};"
                 :: "r"(a), "f"(v0), "f"(v1) : "memory");
}
__device__ __forceinline__ float ldsf(uint32_t a) {
    float v;
    asm volatile("ld.shared.f32 %0, [%1];" : "=f"(v) : "r"(a));
    return v;
}
__device__ __forceinline__ void lds128(uint32_t* r, uint32_t a) {
    asm volatile("ld.shared.v4.b32 {%0,%1,%2,%3}, [%4];"
                 : "=r"(r[0]), "=r"(r[1]), "=r"(r[2]), "=r"(r[3]) : "r"(a));
}
__device__ __forceinline__ void cp_async16(uint32_t smem_a, const float* g) {
    asm volatile("cp.async.ca.shared.global [%0], [%1], 16;"
                 :: "r"(smem_a), "l"(g) : "memory");
}
__device__ __forceinline__ void cp_commit() {
    asm volatile("cp.async.commit_group;" ::: "memory");
}
__device__ __forceinline__ void cp_wait0() {
    asm volatile("cp.async.wait_group 0;" ::: "memory");
}
// f16-accumulate MMA: c/d are 2 b32 regs (row r1 pair in c[0], row r2 in c[1])
__device__ __forceinline__ void mma16816h(uint32_t* c, uint32_t a0, uint32_t a1,
                                          uint32_t a2, uint32_t a3,
                                          uint32_t b0, uint32_t b1) {
    asm volatile(
        "mma.sync.aligned.m16n8k16.row.col.f16.f16.f16.f16 "
        "{%0,%1}, {%2,%3,%4,%5}, {%6,%7}, {%0,%1};"
        : "+r"(c[0]), "+r"(c[1])
        : "r"(a0), "r"(a1), "r"(a2), "r"(a3), "r"(b0), "r"(b1));
}

// issue the 8 cp.asyncs staging one pass's x & y into a stage buffer
__device__ __forceinline__ void issue_stage(uint32_t stg, const float* Xp,
                                            const float* Yp, int tid) {
#pragma unroll
    for (int it = 0; it < 4; it++) {
        const int idx = tid + it * 256;        // float4 idx, 0..1023
        const int b_l = idx >> 8;
        const int i   = (idx >> 3) & 31;
        const int d4  = (idx & 7) * 4;
        const uint32_t off = (uint32_t)(i * XY_STRIDE + b_l * 32 + d4) * 4;
        cp_async16(stg + off,         Xp + idx * 4);
        cp_async16(stg + XS_SZ + off, Yp + idx * 4);
    }
}

__global__ void __launch_bounds__(THREADS, 1)
cin_kernel(const float* __restrict__ X, const float* __restrict__ Y,
           const float* __restrict__ Kmat, float* __restrict__ out_mat,
           float* __restrict__ out_fin) {
    extern __shared__ char smem[];
    const uint32_t sb = smem_u32(smem);
    const int tid  = threadIdx.x;
    const int w    = tid >> 5;
    const int lane = tid & 31;
    const int g    = lane >> 2;     // row group within fragment
    const int t3   = lane & 3;      // col group within fragment
    const int wh   = w & 3;         // row-block (32 rows) 0..3
    const int ch   = w >> 2;        // c-half (0: c0..31, 1: c32..63)
    int rows[4];
    rows[0] = wh * 32 + g;          // tile0 rows: rows[0], rows[1]
    rows[1] = rows[0] + 8;
    rows[2] = rows[0] + 16;         // tile1 rows: rows[2], rows[3]
    rows[3] = rows[0] + 24;

    // per-warp base of the B fragment stream in KP
    const uint32_t kpb = sb + SM_KP + (uint32_t)ch * 1024 + lane * 16;

    // ---------------- prologue: stage first pass via cp.async ---------------
    issue_stage(sb + SM_STG, X + blockIdx.x * 4096, Y + blockIdx.x * 4096, tid);
    cp_commit();

    // ---------------- stage kernel into fragment-packed fp16 SMEM -----------
    // word layout: addr = ((s*4 + q)*32 + l)*16 + w_in*4
    //   s: k16-step (0..63), q = chunk (= ch*2 + q'),
    //   chunk covers frags t=2q,2q+1: n = t*8 + (l>>2), k=(l&3)*2+{0,1}+8*hi
    {
        const float4* K4 = reinterpret_cast<const float4*>(Kmat);
        for (int it = 0; it < 64; it++) {
            const int idx  = tid + it * 256;     // float4 index
            const float4 v = K4[idx];
            const int flat = idx * 4;
            const int c    = flat >> 10;
            const int Kk   = flat & 1023;
            const int s    = Kk >> 4;
            const int kk   = Kk & 15;            // multiple of 4
            const int tt   = c >> 3;
            const int q    = tt >> 1;
            const int hi   = kk >> 3;
            const int w_in = (tt & 1) * 2 + hi;
            const int l0   = (c & 7) * 4 + ((kk & 7) >> 1);
            const uint32_t addr =
                sb + SM_KP + (((s * 4 + q) * 32 + l0) << 4) + (w_in << 2);
            sts32(addr,      cvt2(v.y, v.x));
            sts32(addr + 16, cvt2(v.w, v.z));    // next l
        }
    }

    // ---------------- persistent loop over passes ---------------------------
    int q = 0;
    for (int p = blockIdx.x; p < N_PASSES; p += GRID, q ^= 1) {
        cp_wait0();          // stage[q] data arrived
        __syncthreads();     // ...visible to all warps; prev epi fully done

        const uint32_t stg = sb + SM_STG + (uint32_t)q * STG_SZ;
        const uint32_t xs  = stg;
        const uint32_t ys  = stg + XS_SZ;

        // per-thread y registers: yA[r][qq],
        // j = 2*t3 + (qq&1) + ((qq>>1)&1)*8 + (qq>>2)*16
        float yA[4][8];
#pragma unroll
        for (int qq = 0; qq < 8; qq++) {
            const int j =
                2 * t3 + (qq & 1) + ((qq >> 1) & 1) * 8 + (qq >> 2) * 16;
            const uint32_t jb = ys + (uint32_t)(j * XY_STRIDE) * 4;
#pragma unroll
            for (int r = 0; r < 4; r++)
                yA[r][qq] = ldsf(jb + (uint32_t)rows[r] * 4);
        }

        // prefetch next pass's stage into the other buffer
        {
            const int pn = p + GRID;
            if (pn < N_PASSES)
                issue_stage(sb + SM_STG + (uint32_t)(q ^ 1) * STG_SZ,
                            X + pn * 4096, Y + pn * 4096, tid);
            cp_commit();
        }

        float acc[32];                 // fp32 master accumulators
        uint32_t hacc[16];             // f16x2 mma accumulators (4-step window)
#pragma unroll
        for (int z = 0; z < 32; z++) acc[z] = 0.0f;
#pragma unroll
        for (int z = 0; z < 16; z++) hacc[z] = 0u;

        // ---------------- mainloop: i = 0..31, two k16-steps per i ----------
#pragma unroll 2
        for (int i = 0; i < 32; i++) {
            const uint32_t xb = xs + (uint32_t)(i * XY_STRIDE) * 4;
            float xf[4];
#pragma unroll
            for (int r = 0; r < 4; r++)
                xf[r] = ldsf(xb + (uint32_t)rows[r] * 4);
#pragma unroll
            for (int h = 0; h < 2; h++) {
                const int s  = i * 2 + h;
                const int yb = h * 4;
                uint32_t bb[8];
                const uint32_t bbase = kpb + (uint32_t)s * 2048;
                lds128(bb + 0, bbase);
                lds128(bb + 4, bbase + 512);
#pragma unroll
                for (int m = 0; m < 2; m++) {
                    const uint32_t a0 = cvt2(xf[2 * m]     * yA[2 * m][yb + 1],
                                             xf[2 * m]     * yA[2 * m][yb + 0]);
                    const uint32_t a1 = cvt2(xf[2 * m + 1] * yA[2 * m + 1][yb + 1],
                                             xf[2 * m + 1] * yA[2 * m + 1][yb + 0]);
                    const uint32_t a2 = cvt2(xf[2 * m]     * yA[2 * m][yb + 3],
                                             xf[2 * m]     * yA[2 * m][yb + 2]);
                    const uint32_t a3 = cvt2(xf[2 * m + 1] * yA[2 * m + 1][yb + 3],
                                             xf[2 * m + 1] * yA[2 * m + 1][yb + 2]);
#pragma unroll
                    for (int f = 0; f < 4; f++) {
                        const int bi = (f >> 1) * 4 + (f & 1) * 2;
                        mma16816h(hacc + (m * 4 + f) * 2, a0, a1, a2, a3,
                                  bb[bi], bb[bi + 1]);
                    }
                }
                // ---- flush f16 accumulators to fp32 every 4 k16-steps ----
                if ((s & 3) == 3) {
#pragma unroll
                    for (int tt = 0; tt < 8; tt++) {
#pragma unroll
                        for (int hb = 0; hb < 2; hb++) {
                            const __half2 hv = *reinterpret_cast<const __half2*>(
                                &hacc[tt * 2 + hb]);
                            const float2 v = __half22float2(hv);
                            acc[tt * 4 + hb * 2 + 0] += v.x;
                            acc[tt * 4 + hb * 2 + 1] += v.y;
                            hacc[tt * 2 + hb] = 0u;
                        }
                    }
                }
            }
        }

        __syncthreads();   // all warps done reading xs/ys; BUF aliases stg

        // ---------------- epilogue: frags -> padded SMEM (BUF = stg) --------
#pragma unroll
        for (int m = 0; m < 2; m++) {
#pragma unroll
            for (int f = 0; f < 4; f++) {
                const int c_lo = ch * 32 + f * 8 + 2 * t3;   // even
                const float* a = acc + (m * 4 + f) * 4;
                sts64f(stg + (uint32_t)(rows[2 * m]     * BUF_STRIDE + c_lo) * 4,
                       a[0], a[1]);
                sts64f(stg + (uint32_t)(rows[2 * m + 1] * BUF_STRIDE + c_lo) * 4,
                       a[2], a[3]);
            }
        }
        __syncthreads();

        // ---------------- epi: one (b,c) row of 32 d's per thread -----------
        {
            const int b_l = tid >> 6;           // 0..3
            const int c   = tid & 63;
            const int b   = p * 4 + b_l;
            float* dst = out_mat + ((size_t)b * C_DIM + c) * D_DIM;
            const uint32_t rb =
                stg + (uint32_t)(b_l * 32 * BUF_STRIDE + c) * 4;
            float srow = 0.0f;
#pragma unroll
            for (int g4 = 0; g4 < 8; g4++) {
                const uint32_t a = rb + (uint32_t)(g4 * 4 * BUF_STRIDE) * 4;
                float v0 = ldsf(a);
                float v1 = ldsf(a + BUF_STRIDE * 4);
                float v2 = ldsf(a + 2 * BUF_STRIDE * 4);
                float v3 = ldsf(a + 3 * BUF_STRIDE * 4);
                *reinterpret_cast<float4*>(dst + g4 * 4) =
                    make_float4(v0, v1, v2, v3);
                srow += (v0 + v1) + (v2 + v3);
            }
            out_fin[b * C_DIM + c] = srow;
        }
    }
}

}  // namespace cin

extern "C" void kernel_launch(void* const* d_in, const int* in_sizes, int n_in,
                              void* d_out, int out_size) {
    // Expected order: x [B,H1,D], y [B,H2,D], kernel [C,H1,H2].
    // Defensive remap: kernel is uniquely the 65536-element input.
    const float* x = (const float*)d_in[0];
    const float* y = (const float*)d_in[1];
    const float* k = (const float*)d_in[2];
    if (n_in == 3) {
        if (in_sizes[0] == C_DIM * H_DIM * H_DIM) {
            k = (const float*)d_in[0]; x = (const float*)d_in[1]; y = (const float*)d_in[2];
        } else if (in_sizes[1] == C_DIM * H_DIM * H_DIM) {
            x = (const float*)d_in[0]; k = (const float*)d_in[1]; y = (const float*)d_in[2];
        }
    }
    float* out_mat = (float*)d_out;
    float* out_fin = out_mat + (size_t)B_DIM * C_DIM * D_DIM;

    cudaFuncSetAttribute(cin::cin_kernel,
                         cudaFuncAttributeMaxDynamicSharedMemorySize,
                         cin::SMEM_TOTAL);
    cin::cin_kernel<<<cin::GRID, cin::THREADS, cin::SMEM_TOTAL>>>(
        x, y, k, out_mat, out_fin);
}

// round 14
// speedup vs baseline: 1.1694x; 1.1694x over previous
#include <cuda_runtime.h>
#include <cstdint>

// ============================================================================
// CINLayer: out_mat[b,c,d] = sum_{i,j} kernel[c,i,j] * x[b,i,d] * y[b,j,d]
//           final[b,c]     = sum_d out_mat[b,c,d]
// GEMM mapping: Z[(b,d),(i,j)] = x[b,i,d]*y[b,j,d] (built in regs, fp16)
//               out = Z(131072 x 1024) @ kernel^T(1024 x 64)
// via mma.sync.m16n8k16.f32.f16.f16.f32.
// R12: kill the F2FP converts in the mainloop. Evidence across R4/R7/R8/R11:
//      runtime ranks exactly with cvt.f16x2.f32 count per HMMA (rt~8, lat~20
//      on the critical path). Pre-round y into 8 packed f16x2 regs per pass,
//      dup-convert x once per i, and build A-fragments with one mul.rn.f16x2
//      (rt2 / lat4) each. Mainloop/step: 4 LDS.128 + 4 HMUL2 + 8 HMMA.
//      Chassis: R4 16x64 warp tile + R8 cp.async staging/alias epilogue.
// ============================================================================

#define B_DIM 4096
#define H_DIM 32
#define C_DIM 64
#define D_DIM 32

namespace cin {

constexpr int THREADS   = 256;
constexpr int GRID      = 148;
constexpr int PASS_ROWS = 128;                          // 4 b's x 32 d per pass
constexpr int N_PASSES  = (B_DIM * D_DIM) / PASS_ROWS;  // 1024
constexpr int KSTEPS    = 64;                           // K=1024 / k16

// SMEM (bytes)
constexpr int SM_KP   = 0;                      // packed fp16 kernel: 128KB
constexpr int KP_SZ   = KSTEPS * 4 * 32 * 16;   // 131072
constexpr int XY_STRIDE = 132;                  // stage row stride (words)
constexpr int XS_SZ   = 32 * XY_STRIDE * 4;     // 16896
constexpr int STG_SZ  = 2 * XS_SZ;              // x + y = 33792
constexpr int SM_STG  = SM_KP + KP_SZ;          // two parity buffers
// epilogue buffer aliases the CURRENT (just consumed) stage buffer
constexpr int BUF_STRIDE = 66;                  // even; 128*66*4 = 33792 = STG_SZ
static_assert(PASS_ROWS * BUF_STRIDE * 4 <= STG_SZ, "BUF must fit stage buffer");
constexpr unsigned SMEM_TOTAL = (unsigned)(SM_STG + 2 * STG_SZ);   // 198656

__device__ __forceinline__ uint32_t smem_u32(const void* p) {
    uint32_t a;
    asm("{ .reg .u64 t; cvta.to.shared.u64 t, %1; cvt.u32.u64 %0, t; }"
        : "=r"(a) : "l"(p));
    return a;
}
// pack two f32 -> f16x2 (hi = first arg -> high half)
__device__ __forceinline__ uint32_t cvt2(float hi, float lo) {
    uint32_t r;
    asm("cvt.rn.f16x2.f32 %0, %1, %2;" : "=r"(r) : "f"(hi), "f"(lo));
    return r;
}
// packed fp16 multiply (fixed-latency fma-class: rt2, lat4)
__device__ __forceinline__ uint32_t hmul2(uint32_t a, uint32_t b) {
    uint32_t r;
    asm("mul.rn.f16x2 %0, %1, %2;" : "=r"(r) : "r"(a), "r"(b));
    return r;
}
__device__ __forceinline__ void sts32(uint32_t a, uint32_t v) {
    asm volatile("st.shared.b32 [%0], %1;" :: "r"(a), "r"(v) : "memory");
}
__device__ __forceinline__ void sts64f(uint32_t a, float v0, float v1) {
    asm volatile("st.shared.v2.f32 [%0], {%1,%2};"
                 :: "r"(a), "f"(v0), "f"(v1) : "memory");
}
__device__ __forceinline__ float ldsf(uint32_t a) {
    float v;
    asm volatile("ld.shared.f32 %0, [%1];" : "=f"(v) : "r"(a));
    return v;
}
__device__ __forceinline__ void lds128(uint32_t* r, uint32_t a) {
    asm volatile("ld.shared.v4.b32 {%0,%1,%2,%3}, [%4];"
                 : "=r"(r[0]), "=r"(r[1]), "=r"(r[2]), "=r"(r[3]) : "r"(a));
}
__device__ __forceinline__ void cp_async16(uint32_t smem_a, const float* g) {
    asm volatile("cp.async.ca.shared.global [%0], [%1], 16;"
                 :: "r"(smem_a), "l"(g) : "memory");
}
__device__ __forceinline__ void cp_commit() {
    asm volatile("cp.async.commit_group;" ::: "memory");
}
__device__ __forceinline__ void cp_wait0() {
    asm volatile("cp.async.wait_group 0;" ::: "memory");
}
__device__ __forceinline__ void mma16816(float* c, uint32_t a0, uint32_t a1,
                                         uint32_t a2, uint32_t a3,
                                         uint32_t b0, uint32_t b1) {
    asm volatile(
        "mma.sync.aligned.m16n8k16.row.col.f32.f16.f16.f32 "
        "{%0,%1,%2,%3}, {%4,%5,%6,%7}, {%8,%9}, {%0,%1,%2,%3};"
        : "+f"(c[0]), "+f"(c[1]), "+f"(c[2]), "+f"(c[3])
        : "r"(a0), "r"(a1), "r"(a2), "r"(a3), "r"(b0), "r"(b1));
}

// issue the 8 cp.asyncs staging one pass's x & y into a stage buffer
__device__ __forceinline__ void issue_stage(uint32_t stg, const float* Xp,
                                            const float* Yp, int tid) {
#pragma unroll
    for (int it = 0; it < 4; it++) {
        const int idx = tid + it * 256;        // float4 idx, 0..1023
        const int b_l = idx >> 8;
        const int i   = (idx >> 3) & 31;
        const int d4  = (idx & 7) * 4;
        const uint32_t off = (uint32_t)(i * XY_STRIDE + b_l * 32 + d4) * 4;
        cp_async16(stg + off,         Xp + idx * 4);
        cp_async16(stg + XS_SZ + off, Yp + idx * 4);
    }
}

__global__ void __launch_bounds__(THREADS, 1)
cin_kernel(const float* __restrict__ X, const float* __restrict__ Y,
           const float* __restrict__ Kmat, float* __restrict__ out_mat,
           float* __restrict__ out_fin) {
    extern __shared__ char smem[];
    const uint32_t sb = smem_u32(smem);
    const int tid  = threadIdx.x;
    const int w    = tid >> 5;
    const int lane = tid & 31;
    const int g    = lane >> 2;     // row group within fragment
    const int t3   = lane & 3;      // col group within fragment
    const int r1   = w * 16 + g;    // pass-local row 1 (R4 16x64 warp tile)
    const int r2   = r1 + 8;        // pass-local row 2

    // per-warp base of the B fragment stream in KP (all 4 chunks)
    const uint32_t kpb = sb + SM_KP + lane * 16;

    // ---------------- prologue: stage first pass via cp.async ---------------
    issue_stage(sb + SM_STG, X + blockIdx.x * 4096, Y + blockIdx.x * 4096, tid);
    cp_commit();

    // ---------------- stage kernel into fragment-packed fp16 SMEM -----------
    // word layout: addr = ((s*4 + q)*32 + l)*16 + w_in*4
    //   s: k16-step (0..63), q: LDS.128 chunk (0..3),
    //   chunk covers frags t=2q,2q+1: n = t*8 + (l>>2), k=(l&3)*2+{0,1}+8*hi
    {
        const float4* K4 = reinterpret_cast<const float4*>(Kmat);
        for (int it = 0; it < 64; it++) {
            const int idx  = tid + it * 256;     // float4 index
            const float4 v = K4[idx];
            const int flat = idx * 4;
            const int c    = flat >> 10;
            const int Kk   = flat & 1023;
            const int s    = Kk >> 4;
            const int kk   = Kk & 15;            // multiple of 4
            const int tt   = c >> 3;
            const int q    = tt >> 1;
            const int hi   = kk >> 3;
            const int w_in = (tt & 1) * 2 + hi;
            const int l0   = (c & 7) * 4 + ((kk & 7) >> 1);
            const uint32_t addr =
                sb + SM_KP + (((s * 4 + q) * 32 + l0) << 4) + (w_in << 2);
            sts32(addr,      cvt2(v.y, v.x));
            sts32(addr + 16, cvt2(v.w, v.z));    // next l
        }
    }

    // ---------------- persistent loop over passes ---------------------------
    int q = 0;
    for (int p = blockIdx.x; p < N_PASSES; p += GRID, q ^= 1) {
        cp_wait0();          // stage[q] data arrived
        __syncthreads();     // ...visible to all warps; prev epi fully done

        const uint32_t stg = sb + SM_STG + (uint32_t)q * STG_SZ;
        const uint32_t xs  = stg;
        const uint32_t ys  = stg + XS_SZ;

        // pre-rounded y fragments: yh2[r][u] = f16x2(y[j0+1] hi, y[j0] lo),
        // j0 = 2*t3 + (u&1)*8 + (u>>1)*16.  8 cvt2 per thread per pass.
        uint32_t yh2[2][4];
#pragma unroll
        for (int u = 0; u < 4; u++) {
            const int j0 = 2 * t3 + (u & 1) * 8 + (u >> 1) * 16;
            const uint32_t b0 = ys + (uint32_t)(j0 * XY_STRIDE) * 4;
            const uint32_t b1 = ys + (uint32_t)((j0 + 1) * XY_STRIDE) * 4;
            yh2[0][u] = cvt2(ldsf(b1 + (uint32_t)r1 * 4),
                             ldsf(b0 + (uint32_t)r1 * 4));
            yh2[1][u] = cvt2(ldsf(b1 + (uint32_t)r2 * 4),
                             ldsf(b0 + (uint32_t)r2 * 4));
        }

        // prefetch next pass's stage into the other buffer
        {
            const int pn = p + GRID;
            if (pn < N_PASSES)
                issue_stage(sb + SM_STG + (uint32_t)(q ^ 1) * STG_SZ,
                            X + pn * 4096, Y + pn * 4096, tid);
            cp_commit();
        }

        float acc[32];
#pragma unroll
        for (int z = 0; z < 32; z++) acc[z] = 0.0f;

        // ---------------- mainloop: i = 0..31, two k16-steps per i ----------
        // per step: 4 LDS.128 (B) + 4 HMUL2 (A frags) + 8 HMMA. No converts.
#pragma unroll 4
        for (int i = 0; i < 32; i++) {
            const uint32_t xb = xs + (uint32_t)(i * XY_STRIDE) * 4;
            const float xf0 = ldsf(xb + (uint32_t)r1 * 4);
            const float xf1 = ldsf(xb + (uint32_t)r2 * 4);
            const uint32_t xh0 = cvt2(xf0, xf0);   // dup fp16 pair
            const uint32_t xh1 = cvt2(xf1, xf1);
#pragma unroll
            for (int h = 0; h < 2; h++) {
                const int s = i * 2 + h;
                uint32_t bb[16];
                const uint32_t bbase = kpb + (uint32_t)s * 2048;
                lds128(bb + 0,  bbase + 0 * 512);
                lds128(bb + 4,  bbase + 1 * 512);
                lds128(bb + 8,  bbase + 2 * 512);
                lds128(bb + 12, bbase + 3 * 512);

                const uint32_t a0 = hmul2(xh0, yh2[0][2 * h + 0]);
                const uint32_t a1 = hmul2(xh1, yh2[1][2 * h + 0]);
                const uint32_t a2 = hmul2(xh0, yh2[0][2 * h + 1]);
                const uint32_t a3 = hmul2(xh1, yh2[1][2 * h + 1]);
#pragma unroll
                for (int tt = 0; tt < 8; tt++) {
                    const int bi = (tt >> 1) * 4 + (tt & 1) * 2;
                    mma16816(acc + tt * 4, a0, a1, a2, a3,
                             bb[bi], bb[bi + 1]);
                }
            }
        }

        __syncthreads();   // all warps done reading xs/ys; BUF aliases stg

        // ---------------- epilogue: frags -> padded SMEM (BUF = stg) --------
#pragma unroll
        for (int tt = 0; tt < 8; tt++) {
            const int c_lo = tt * 8 + 2 * t3;   // even
            const float* a = acc + tt * 4;
            sts64f(stg + (uint32_t)(r1 * BUF_STRIDE + c_lo) * 4, a[0], a[1]);
            sts64f(stg + (uint32_t)(r2 * BUF_STRIDE + c_lo) * 4, a[2], a[3]);
        }
        __syncthreads();

        // ---------------- epi: one (b,c) row of 32 d's per thread -----------
        {
            const int b_l = tid >> 6;           // 0..3
            const int c   = tid & 63;
            const int b   = p * 4 + b_l;
            float* dst = out_mat + ((size_t)b * C_DIM + c) * D_DIM;
            const uint32_t rb =
                stg + (uint32_t)(b_l * 32 * BUF_STRIDE + c) * 4;
            float srow = 0.0f;
#pragma unroll
            for (int g4 = 0; g4 < 8; g4++) {
                const uint32_t a = rb + (uint32_t)(g4 * 4 * BUF_STRIDE) * 4;
                float v0 = ldsf(a);
                float v1 = ldsf(a + BUF_STRIDE * 4);
                float v2 = ldsf(a + 2 * BUF_STRIDE * 4);
                float v3 = ldsf(a + 3 * BUF_STRIDE * 4);
                *reinterpret_cast<float4*>(dst + g4 * 4) =
                    make_float4(v0, v1, v2, v3);
                srow += (v0 + v1) + (v2 + v3);
            }
            out_fin[b * C_DIM + c] = srow;
        }
    }
}

}  // namespace cin

extern "C" void kernel_launch(void* const* d_in, const int* in_sizes, int n_in,
                              void* d_out, int out_size) {
    // Expected order: x [B,H1,D], y [B,H2,D], kernel [C,H1,H2].
    // Defensive remap: kernel is uniquely the 65536-element input.
    const float* x = (const float*)d_in[0];
    const float* y = (const float*)d_in[1];
    const float* k = (const float*)d_in[2];
    if (n_in == 3) {
        if (in_sizes[0] == C_DIM * H_DIM * H_DIM) {
            k = (const float*)d_in[0]; x = (const float*)d_in[1]; y = (const float*)d_in[2];
        } else if (in_sizes[1] == C_DIM * H_DIM * H_DIM) {
            x = (const float*)d_in[0]; k = (const float*)d_in[1]; y = (const float*)d_in[2];
        }
    }
    float* out_mat = (float*)d_out;
    float* out_fin = out_mat + (size_t)B_DIM * C_DIM * D_DIM;

    cudaFuncSetAttribute(cin::cin_kernel,
                         cudaFuncAttributeMaxDynamicSharedMemorySize,
                         cin::SMEM_TOTAL);
    cin::cin_kernel<<<cin::GRID, cin::THREADS, cin::SMEM_TOTAL>>>(
        x, y, k, out_mat, out_fin);
}